// round 4
// baseline (speedup 1.0000x reference)
#include <cuda_runtime.h>
#include <cuda_bf16.h>
#include <cstdint>

// ---------------------------------------------------------------------------
// Problem constants
// ---------------------------------------------------------------------------
#define BATCH   4
#define N1      2048
#define N2      8192
#define C1      128
#define C2      64
#define KP      15
#define FOUT    128
#define NSAMP   16
#define NQ      (BATCH * N2)          // 32768 queries
#define KDIM    (KP * C1)             // 1920
#define OUTC    (FOUT + C2)           // 192
#define NCHUNK  (KDIM / 64)           // 30 K-chunks of 64 bf16

// Scratch (device globals)
__device__ int            g_idx[NQ * NSAMP];
__device__ __nv_bfloat16  g_a_hi[(size_t)NQ * KDIM];     // split wf, row-major (q, kc)
__device__ __nv_bfloat16  g_a_lo[(size_t)NQ * KDIM];
__device__ __nv_bfloat16  g_b_hi[(size_t)FOUT * KDIM];   // W^T, row-major (f, kc)
__device__ __nv_bfloat16  g_b_lo[(size_t)FOUT * KDIM];

// ---------------------------------------------------------------------------
// Helpers
// ---------------------------------------------------------------------------
__device__ __forceinline__ uint32_t smem_u32(const void* p) {
    uint32_t a;
    asm("{ .reg .u64 t; cvta.to.shared.u64 t, %1; cvt.u32.u64 %0, t; }"
        : "=r"(a) : "l"(p));
    return a;
}
__device__ __forceinline__ void ldsm4(uint32_t* r, uint32_t addr) {
    asm volatile("ldmatrix.sync.aligned.m8n8.x4.shared.b16 {%0,%1,%2,%3}, [%4];"
                 : "=r"(r[0]), "=r"(r[1]), "=r"(r[2]), "=r"(r[3]) : "r"(addr));
}
__device__ __forceinline__ void mma16816(float* c, const uint32_t* a,
                                         const uint32_t* b) {
    asm volatile(
        "mma.sync.aligned.m16n8k16.row.col.f32.bf16.bf16.f32 "
        "{%0,%1,%2,%3}, {%4,%5,%6,%7}, {%8,%9}, {%0,%1,%2,%3};"
        : "+f"(c[0]), "+f"(c[1]), "+f"(c[2]), "+f"(c[3])
        : "r"(a[0]), "r"(a[1]), "r"(a[2]), "r"(a[3]), "r"(b[0]), "r"(b[1]));
}

// ---------------------------------------------------------------------------
// Kernel 1: brute-force kNN, unsorted top-16 with dmax tracking.
// One thread per query; xyz1 of the batch cached in smem (24 KB).
// ---------------------------------------------------------------------------
__global__ __launch_bounds__(128) void knn_kernel(
    const float* __restrict__ xyz1, const float* __restrict__ xyz2)
{
    __shared__ float sx[N1], sy[N1], sz[N1];
    const int b = blockIdx.y;
    const float* p1 = xyz1 + (size_t)b * N1 * 3;
    for (int i = threadIdx.x; i < N1; i += blockDim.x) {
        sx[i] = p1[i * 3 + 0];
        sy[i] = p1[i * 3 + 1];
        sz[i] = p1[i * 3 + 2];
    }
    __syncthreads();

    const int qn = blockIdx.x * blockDim.x + threadIdx.x;
    const int q = b * N2 + qn;
    const float qx = xyz2[q * 3 + 0];
    const float qy = xyz2[q * 3 + 1];
    const float qz = xyz2[q * 3 + 2];

    float dk[NSAMP];
    int   ik[NSAMP];

    // fill first 16 slots directly
    #pragma unroll
    for (int p = 0; p < NSAMP; ++p) {
        float dx = qx - sx[p];
        float dy = qy - sy[p];
        float dz = qz - sz[p];
        dk[p] = fmaf(dx, dx, fmaf(dy, dy, dz * dz));
        ik[p] = p;
    }
    float dmax = dk[0];
    #pragma unroll
    for (int p = 1; p < NSAMP; ++p) dmax = fmaxf(dmax, dk[p]);

    #pragma unroll 4
    for (int j = NSAMP; j < N1; ++j) {
        float dx = qx - sx[j];
        float dy = qy - sy[j];
        float dz = qz - sz[j];
        float d2 = fmaf(dx, dx, fmaf(dy, dy, dz * dz));
        if (d2 < dmax) {
            // replace first slot holding dmax (static-index predicated scan)
            bool done = false;
            #pragma unroll
            for (int p = 0; p < NSAMP; ++p) {
                bool hit = (!done) && (dk[p] == dmax);
                if (hit) { dk[p] = d2; ik[p] = j; done = true; }
            }
            // recompute running max
            dmax = dk[0];
            #pragma unroll
            for (int p = 1; p < NSAMP; ++p) dmax = fmaxf(dmax, dk[p]);
        }
    }

    int* o = g_idx + q * NSAMP;
    #pragma unroll
    for (int p = 0; p < NSAMP; ++p) o[p] = ik[p];
}

// ---------------------------------------------------------------------------
// Kernel 2: kernel-point weights + weighted aggregation, bf16-split output.
// 64 threads per query; thread t owns channels (2t, 2t+1) -> float2 gathers,
// packed bf16x2 4-byte stores.
// ---------------------------------------------------------------------------
__global__ __launch_bounds__(64) void wf_kernel(
    const float* __restrict__ xyz1, const float* __restrict__ feat1,
    const float* __restrict__ xyz2, const float* __restrict__ kp)
{
    const int q = blockIdx.x;
    const int b = q >> 13;
    const int t = threadIdx.x;

    __shared__ int   sid[NSAMP];
    __shared__ float skp[KP * 3];
    __shared__ float sw[NSAMP][KP];

    if (t < KP * 3) skp[t] = kp[t];
    if (t < NSAMP)  sid[t] = g_idx[q * NSAMP + t];
    __syncthreads();

    if (t < NSAMP) {
        const int ni = sid[t];
        const float rx = xyz1[((size_t)b * N1 + ni) * 3 + 0] - xyz2[q * 3 + 0];
        const float ry = xyz1[((size_t)b * N1 + ni) * 3 + 1] - xyz2[q * 3 + 1];
        const float rz = xyz1[((size_t)b * N1 + ni) * 3 + 2] - xyz2[q * 3 + 2];
        #pragma unroll
        for (int k = 0; k < KP; ++k) {
            float dx = rx - skp[k * 3 + 0];
            float dy = ry - skp[k * 3 + 1];
            float dz = rz - skp[k * 3 + 2];
            float sq = dx * dx + dy * dy + dz * dz;
            float dist = sqrtf(fmaxf(sq, 1e-12f));
            sw[t][k] = fmaxf(0.0f, 1.0f - dist / 0.2f);
        }
    }
    __syncthreads();

    const float* fb = feat1 + (size_t)b * N1 * C1;
    float2 f[NSAMP];
    #pragma unroll
    for (int s = 0; s < NSAMP; ++s)
        f[s] = *(const float2*)(fb + (size_t)sid[s] * C1 + 2 * t);

    float ax[KP], ay[KP];
    #pragma unroll
    for (int k = 0; k < KP; ++k) { ax[k] = 0.0f; ay[k] = 0.0f; }
    #pragma unroll
    for (int s = 0; s < NSAMP; ++s) {
        const float fx = f[s].x, fy = f[s].y;
        #pragma unroll
        for (int k = 0; k < KP; ++k) {
            float w = sw[s][k];
            ax[k] = fmaf(w, fx, ax[k]);
            ay[k] = fmaf(w, fy, ay[k]);
        }
    }

    const size_t qbase = (size_t)q * KDIM + 2 * t;
    #pragma unroll
    for (int k = 0; k < KP; ++k) {
        float vx = ax[k], vy = ay[k];
        __nv_bfloat16 hx = __float2bfloat16(vx);
        __nv_bfloat16 hy = __float2bfloat16(vy);
        __nv_bfloat162 hi; hi.x = hx; hi.y = hy;
        __nv_bfloat162 lo;
        lo.x = __float2bfloat16(vx - __bfloat162float(hx));
        lo.y = __float2bfloat16(vy - __bfloat162float(hy));
        *(__nv_bfloat162*)(g_a_hi + qbase + k * C1) = hi;
        *(__nv_bfloat162*)(g_a_lo + qbase + k * C1) = lo;
    }
}

// ---------------------------------------------------------------------------
// Kernel 2b: split + transpose W -> B^T (f, kc), bf16 hi/lo
// ---------------------------------------------------------------------------
__global__ __launch_bounds__(256) void wprep_kernel(const float* __restrict__ W)
{
    const int i = blockIdx.x * blockDim.x + threadIdx.x;
    if (i >= KDIM * FOUT) return;
    const int kc = i / FOUT;
    const int f  = i % FOUT;
    float w = W[i];
    __nv_bfloat16 h = __float2bfloat16(w);
    g_b_hi[(size_t)f * KDIM + kc] = h;
    g_b_lo[(size_t)f * KDIM + kc] = __float2bfloat16(w - __bfloat162float(h));
}

// ---------------------------------------------------------------------------
// Kernel 3: mma.sync bf16 GEMM (2-way split, 3 products), relu epilogue.
// M=32768 (128 CTAs of 256 rows), N=128, K=1920 in 30 chunks of 64.
// 8 warps in 4(M)x2(N): warp tile 64x64. Double-buffered cp.async, 192KB smem.
// ---------------------------------------------------------------------------
#define A_SUB       32768               // 256 rows x 128B
#define B_SUB       16384               // 128 rows x 128B
#define STAGE_BYTES (2 * A_SUB + 2 * B_SUB)   // 96KB
#define GEMM_SMEM   (2 * STAGE_BYTES)          // 192KB

__global__ __launch_bounds__(256, 1)
void gemm_kernel(float* __restrict__ out)
{
    extern __shared__ __align__(1024) char dsmem[];

    const int tid = threadIdx.x;
    const int wid = tid >> 5;
    const int L   = tid & 31;
    const int m0  = blockIdx.x * 256;
    const int wm  = wid & 3;              // 0..3 (M, 64 rows each)
    const int wn  = wid >> 2;             // 0..1 (N, 64 cols each)

    const uint32_t base = smem_u32(dsmem);

    const char* srcA_hi = (const char*)g_a_hi + (size_t)m0 * (KDIM * 2);
    const char* srcA_lo = (const char*)g_a_lo + (size_t)m0 * (KDIM * 2);
    const char* srcB_hi = (const char*)g_b_hi;
    const char* srcB_lo = (const char*)g_b_lo;

    auto load_stage = [&](int chunk, int buf) {
        const uint32_t sbase = base + buf * STAGE_BYTES;
        // A hi/lo: 256 rows x 8 x 16B = 2048 ops each
        #pragma unroll
        for (int arr = 0; arr < 2; ++arr) {
            const char* s = arr ? srcA_lo : srcA_hi;
            const uint32_t so = sbase + arr * A_SUB;
            #pragma unroll
            for (int v = 0; v < 8; ++v) {
                int idx = v * 256 + tid;          // 0..2047
                int row = idx >> 3;
                int kb  = (idx & 7) << 4;
                const char* g = s + (size_t)row * (KDIM * 2) + chunk * 128 + kb;
                uint32_t sa = so + row * 128 + (kb ^ ((row & 7) << 4));
                asm volatile("cp.async.cg.shared.global [%0], [%1], 16;"
                             :: "r"(sa), "l"(g));
            }
        }
        // B hi/lo: 128 rows x 8 x 16B = 1024 ops each
        #pragma unroll
        for (int arr = 0; arr < 2; ++arr) {
            const char* s = arr ? srcB_lo : srcB_hi;
            const uint32_t so = sbase + 2 * A_SUB + arr * B_SUB;
            #pragma unroll
            for (int v = 0; v < 4; ++v) {
                int idx = v * 256 + tid;          // 0..1023
                int row = idx >> 3;
                int kb  = (idx & 7) << 4;
                const char* g = s + (size_t)row * (KDIM * 2) + chunk * 128 + kb;
                uint32_t sa = so + row * 128 + (kb ^ ((row & 7) << 4));
                asm volatile("cp.async.cg.shared.global [%0], [%1], 16;"
                             :: "r"(sa), "l"(g));
            }
        }
        asm volatile("cp.async.commit_group;" ::: "memory");
    };

    // ldmatrix per-thread offsets
    int aRow = wm * 64 + (L & 15);                  // + mt*16
    int aKb  = (L >> 4) * 16;
    int bRow = wn * 64 + ((L >> 4) << 3) + (L & 7); // + ng*16
    int bKb  = ((L >> 3) & 1) * 16;

    uint32_t aOff[4], aXor[4];
    #pragma unroll
    for (int mt = 0; mt < 4; ++mt) {
        int r = aRow + mt * 16;
        aOff[mt] = r * 128;
        aXor[mt] = (r & 7) << 4;
    }
    uint32_t bOff[4], bXor[4];
    #pragma unroll
    for (int ng = 0; ng < 4; ++ng) {
        int r = bRow + ng * 16;
        bOff[ng] = r * 128;
        bXor[ng] = (r & 7) << 4;
    }

    float acc[4][8][4];
    #pragma unroll
    for (int i = 0; i < 4; ++i)
        #pragma unroll
        for (int j = 0; j < 8; ++j)
            #pragma unroll
            for (int k = 0; k < 4; ++k) acc[i][j][k] = 0.0f;

    load_stage(0, 0);
    load_stage(1, 1);

    for (int i = 0; i < NCHUNK; ++i) {
        const int buf = i & 1;
        if (i + 1 < NCHUNK)
            asm volatile("cp.async.wait_group 1;" ::: "memory");
        else
            asm volatile("cp.async.wait_group 0;" ::: "memory");
        __syncthreads();

        const uint32_t sb  = base + buf * STAGE_BYTES;
        const uint32_t sAh = sb;
        const uint32_t sAl = sb + A_SUB;
        const uint32_t sBh = sb + 2 * A_SUB;
        const uint32_t sBl = sb + 2 * A_SUB + B_SUB;

        #pragma unroll
        for (int ks = 0; ks < 4; ++ks) {
            const uint32_t kA = ks * 32 + aKb;
            const uint32_t kB = ks * 32 + bKb;
            uint32_t ah[4][4], al[4][4];
            #pragma unroll
            for (int mt = 0; mt < 4; ++mt) {
                uint32_t o = aOff[mt] + (kA ^ aXor[mt]);
                ldsm4(ah[mt], sAh + o);
                ldsm4(al[mt], sAl + o);
            }
            #pragma unroll
            for (int ng = 0; ng < 4; ++ng) {
                uint32_t bh[4], bl[4];
                uint32_t o = bOff[ng] + (kB ^ bXor[ng]);
                ldsm4(bh, sBh + o);
                ldsm4(bl, sBl + o);
                #pragma unroll
                for (int mt = 0; mt < 4; ++mt) {
                    #pragma unroll
                    for (int h = 0; h < 2; ++h) {
                        float* c = acc[mt][ng * 2 + h];
                        const uint32_t* fh = &bh[h * 2];
                        const uint32_t* fl = &bl[h * 2];
                        mma16816(c, ah[mt], fh);   // hi*hi
                        mma16816(c, ah[mt], fl);   // hi*lo
                        mma16816(c, al[mt], fh);   // lo*hi
                    }
                }
            }
        }

        __syncthreads();
        if (i + 2 < NCHUNK) load_stage(i + 2, buf);
    }

    // epilogue: relu + store (mma c-frag layout)
    #pragma unroll
    for (int mt = 0; mt < 4; ++mt) {
        #pragma unroll
        for (int nt = 0; nt < 8; ++nt) {
            const float* c = acc[mt][nt];
            int row = m0 + wm * 64 + mt * 16 + (L >> 2);
            int col = wn * 64 + nt * 8 + (L & 3) * 2;
            float2 v0, v1;
            v0.x = fmaxf(c[0], 0.0f); v0.y = fmaxf(c[1], 0.0f);
            v1.x = fmaxf(c[2], 0.0f); v1.y = fmaxf(c[3], 0.0f);
            *(float2*)(out + (size_t)row * OUTC + col)       = v0;
            *(float2*)(out + (size_t)(row + 8) * OUTC + col) = v1;
        }
    }
}

// ---------------------------------------------------------------------------
// Kernel 4: concat features2 into out[:, 128:192]
// ---------------------------------------------------------------------------
__global__ __launch_bounds__(256) void concat_kernel(
    const float* __restrict__ feat2, float* __restrict__ out)
{
    const int i = blockIdx.x * blockDim.x + threadIdx.x;
    if (i >= NQ * (C2 / 4)) return;
    const int q = i >> 4;
    const int j = i & 15;
    float4 v = *(const float4*)(feat2 + (size_t)q * C2 + j * 4);
    *(float4*)(out + (size_t)q * OUTC + FOUT + j * 4) = v;
}

// ---------------------------------------------------------------------------
// Launch
// ---------------------------------------------------------------------------
extern "C" void kernel_launch(void* const* d_in, const int* in_sizes, int n_in,
                              void* d_out, int out_size)
{
    const float* xyz1  = (const float*)d_in[0];
    const float* feat1 = (const float*)d_in[1];
    const float* xyz2  = (const float*)d_in[2];
    const float* feat2 = (const float*)d_in[3];
    const float* kp    = (const float*)d_in[4];
    const float* W     = (const float*)d_in[5];
    float* out = (float*)d_out;

    cudaFuncSetAttribute(gemm_kernel,
                         cudaFuncAttributeMaxDynamicSharedMemorySize, GEMM_SMEM);

    knn_kernel<<<dim3(N2 / 128, BATCH), 128>>>(xyz1, xyz2);
    wf_kernel<<<NQ, 64>>>(xyz1, feat1, xyz2, kp);
    wprep_kernel<<<(KDIM * FOUT + 255) / 256, 256>>>(W);
    gemm_kernel<<<NQ / 256, 256, GEMM_SMEM>>>(out);
    concat_kernel<<<(NQ * (C2 / 4) + 255) / 256, 256>>>(feat2, out);
}

// round 5
// speedup vs baseline: 1.6989x; 1.6989x over previous
#include <cuda_runtime.h>
#include <cuda_bf16.h>
#include <cstdint>

// ---------------------------------------------------------------------------
// Problem constants
// ---------------------------------------------------------------------------
#define BATCH   4
#define N1      2048
#define N2      8192
#define C1      128
#define C2      64
#define KP      15
#define FOUT    128
#define NSAMP   16
#define NQ      (BATCH * N2)          // 32768 queries
#define KDIM    (KP * C1)             // 1920
#define OUTC    (FOUT + C2)           // 192
#define NCHUNK  (KDIM / 64)           // 30 K-chunks of 64 bf16

// Scratch (device globals)
__device__ int            g_idx[NQ * NSAMP];
__device__ __nv_bfloat16  g_a_hi[(size_t)NQ * KDIM];     // split wf, row-major (q, kc)
__device__ __nv_bfloat16  g_a_lo[(size_t)NQ * KDIM];
__device__ __nv_bfloat16  g_b_hi[(size_t)FOUT * KDIM];   // W^T, row-major (f, kc)
__device__ __nv_bfloat16  g_b_lo[(size_t)FOUT * KDIM];

// ---------------------------------------------------------------------------
// Helpers
// ---------------------------------------------------------------------------
__device__ __forceinline__ uint32_t smem_u32(const void* p) {
    uint32_t a;
    asm("{ .reg .u64 t; cvta.to.shared.u64 t, %1; cvt.u32.u64 %0, t; }"
        : "=r"(a) : "l"(p));
    return a;
}
__device__ __forceinline__ void ldsm4(uint32_t* r, uint32_t addr) {
    asm volatile("ldmatrix.sync.aligned.m8n8.x4.shared.b16 {%0,%1,%2,%3}, [%4];"
                 : "=r"(r[0]), "=r"(r[1]), "=r"(r[2]), "=r"(r[3]) : "r"(addr));
}
__device__ __forceinline__ void mma16816(float* c, const uint32_t* a,
                                         const uint32_t* b) {
    asm volatile(
        "mma.sync.aligned.m16n8k16.row.col.f32.bf16.bf16.f32 "
        "{%0,%1,%2,%3}, {%4,%5,%6,%7}, {%8,%9}, {%0,%1,%2,%3};"
        : "+f"(c[0]), "+f"(c[1]), "+f"(c[2]), "+f"(c[3])
        : "r"(a[0]), "r"(a[1]), "r"(a[2]), "r"(a[3]), "r"(b[0]), "r"(b[1]));
}

// ---------------------------------------------------------------------------
// Kernel 1: brute-force kNN (R3 version: 256-thread blocks, bubble insert).
// 24KB smem -> 8 CTAs/SM x 256 thr = full occupancy.
// ---------------------------------------------------------------------------
__global__ __launch_bounds__(256) void knn_kernel(
    const float* __restrict__ xyz1, const float* __restrict__ xyz2)
{
    __shared__ float sx[N1], sy[N1], sz[N1];
    const int b = blockIdx.y;
    const float* p1 = xyz1 + (size_t)b * N1 * 3;
    for (int i = threadIdx.x; i < N1; i += blockDim.x) {
        sx[i] = p1[i * 3 + 0];
        sy[i] = p1[i * 3 + 1];
        sz[i] = p1[i * 3 + 2];
    }
    __syncthreads();

    const int qn = blockIdx.x * blockDim.x + threadIdx.x;
    if (qn >= N2) return;
    const int q = b * N2 + qn;
    const float qx = xyz2[q * 3 + 0];
    const float qy = xyz2[q * 3 + 1];
    const float qz = xyz2[q * 3 + 2];

    float dk[NSAMP];
    int   ik[NSAMP];
    #pragma unroll
    for (int p = 0; p < NSAMP; ++p) { dk[p] = 3.4e38f; ik[p] = 0; }

    for (int j = 0; j < N1; ++j) {
        float dx = qx - sx[j];
        float dy = qy - sy[j];
        float dz = qz - sz[j];
        float d2 = dx * dx + dy * dy + dz * dz;
        if (d2 < dk[NSAMP - 1]) {
            dk[NSAMP - 1] = d2; ik[NSAMP - 1] = j;
            #pragma unroll
            for (int p = NSAMP - 1; p > 0; --p) {
                if (dk[p] < dk[p - 1]) {
                    float td = dk[p]; dk[p] = dk[p - 1]; dk[p - 1] = td;
                    int   ti = ik[p]; ik[p] = ik[p - 1]; ik[p - 1] = ti;
                }
            }
        }
    }

    int* o = g_idx + q * NSAMP;
    #pragma unroll
    for (int p = 0; p < NSAMP; ++p) o[p] = ik[p];
}

// ---------------------------------------------------------------------------
// Kernel 2: kernel-point weights + weighted aggregation, bf16-split output.
// 64 threads per query; thread t owns channels (2t, 2t+1).
// ---------------------------------------------------------------------------
__global__ __launch_bounds__(64) void wf_kernel(
    const float* __restrict__ xyz1, const float* __restrict__ feat1,
    const float* __restrict__ xyz2, const float* __restrict__ kp)
{
    const int q = blockIdx.x;
    const int b = q >> 13;
    const int t = threadIdx.x;

    __shared__ int   sid[NSAMP];
    __shared__ float skp[KP * 3];
    __shared__ float sw[NSAMP][KP];

    if (t < KP * 3) skp[t] = kp[t];
    if (t < NSAMP)  sid[t] = g_idx[q * NSAMP + t];
    __syncthreads();

    if (t < NSAMP) {
        const int ni = sid[t];
        const float rx = xyz1[((size_t)b * N1 + ni) * 3 + 0] - xyz2[q * 3 + 0];
        const float ry = xyz1[((size_t)b * N1 + ni) * 3 + 1] - xyz2[q * 3 + 1];
        const float rz = xyz1[((size_t)b * N1 + ni) * 3 + 2] - xyz2[q * 3 + 2];
        #pragma unroll
        for (int k = 0; k < KP; ++k) {
            float dx = rx - skp[k * 3 + 0];
            float dy = ry - skp[k * 3 + 1];
            float dz = rz - skp[k * 3 + 2];
            float sq = dx * dx + dy * dy + dz * dz;
            float dist = sqrtf(fmaxf(sq, 1e-12f));
            sw[t][k] = fmaxf(0.0f, 1.0f - dist / 0.2f);
        }
    }
    __syncthreads();

    const float* fb = feat1 + (size_t)b * N1 * C1;
    float2 f[NSAMP];
    #pragma unroll
    for (int s = 0; s < NSAMP; ++s)
        f[s] = *(const float2*)(fb + (size_t)sid[s] * C1 + 2 * t);

    float ax[KP], ay[KP];
    #pragma unroll
    for (int k = 0; k < KP; ++k) { ax[k] = 0.0f; ay[k] = 0.0f; }
    #pragma unroll
    for (int s = 0; s < NSAMP; ++s) {
        const float fx = f[s].x, fy = f[s].y;
        #pragma unroll
        for (int k = 0; k < KP; ++k) {
            float w = sw[s][k];
            ax[k] = fmaf(w, fx, ax[k]);
            ay[k] = fmaf(w, fy, ay[k]);
        }
    }

    const size_t qbase = (size_t)q * KDIM + 2 * t;
    #pragma unroll
    for (int k = 0; k < KP; ++k) {
        float vx = ax[k], vy = ay[k];
        __nv_bfloat16 hx = __float2bfloat16(vx);
        __nv_bfloat16 hy = __float2bfloat16(vy);
        __nv_bfloat162 hi; hi.x = hx; hi.y = hy;
        __nv_bfloat162 lo;
        lo.x = __float2bfloat16(vx - __bfloat162float(hx));
        lo.y = __float2bfloat16(vy - __bfloat162float(hy));
        *(__nv_bfloat162*)(g_a_hi + qbase + k * C1) = hi;
        *(__nv_bfloat162*)(g_a_lo + qbase + k * C1) = lo;
    }
}

// ---------------------------------------------------------------------------
// Kernel 2b: split + transpose W -> B^T (f, kc), bf16 hi/lo
// ---------------------------------------------------------------------------
__global__ __launch_bounds__(256) void wprep_kernel(const float* __restrict__ W)
{
    const int i = blockIdx.x * blockDim.x + threadIdx.x;
    if (i >= KDIM * FOUT) return;
    const int kc = i / FOUT;
    const int f  = i % FOUT;
    float w = W[i];
    __nv_bfloat16 h = __float2bfloat16(w);
    g_b_hi[(size_t)f * KDIM + kc] = h;
    g_b_lo[(size_t)f * KDIM + kc] = __float2bfloat16(w - __bfloat162float(h));
}

// ---------------------------------------------------------------------------
// Kernel 3: mma.sync bf16 GEMM (2-way split, 3 products), relu epilogue.
// M=32768 (128 CTAs of 256 rows), N=128, K=1920 in 30 chunks of 64.
// 8 warps in 4(M)x2(N): warp tile 64x64. Double-buffered cp.async, 192KB smem.
// ---------------------------------------------------------------------------
#define A_SUB       32768               // 256 rows x 128B
#define B_SUB       16384               // 128 rows x 128B
#define STAGE_BYTES (2 * A_SUB + 2 * B_SUB)   // 96KB
#define GEMM_SMEM   (2 * STAGE_BYTES)          // 192KB

__global__ __launch_bounds__(256, 1)
void gemm_kernel(float* __restrict__ out)
{
    extern __shared__ __align__(1024) char dsmem[];

    const int tid = threadIdx.x;
    const int wid = tid >> 5;
    const int L   = tid & 31;
    const int m0  = blockIdx.x * 256;
    const int wm  = wid & 3;              // 0..3 (M, 64 rows each)
    const int wn  = wid >> 2;             // 0..1 (N, 64 cols each)

    const uint32_t base = smem_u32(dsmem);

    const char* srcA_hi = (const char*)g_a_hi + (size_t)m0 * (KDIM * 2);
    const char* srcA_lo = (const char*)g_a_lo + (size_t)m0 * (KDIM * 2);
    const char* srcB_hi = (const char*)g_b_hi;
    const char* srcB_lo = (const char*)g_b_lo;

    auto load_stage = [&](int chunk, int buf) {
        const uint32_t sbase = base + buf * STAGE_BYTES;
        #pragma unroll
        for (int arr = 0; arr < 2; ++arr) {
            const char* s = arr ? srcA_lo : srcA_hi;
            const uint32_t so = sbase + arr * A_SUB;
            #pragma unroll
            for (int v = 0; v < 8; ++v) {
                int idx = v * 256 + tid;          // 0..2047
                int row = idx >> 3;
                int kb  = (idx & 7) << 4;
                const char* g = s + (size_t)row * (KDIM * 2) + chunk * 128 + kb;
                uint32_t sa = so + row * 128 + (kb ^ ((row & 7) << 4));
                asm volatile("cp.async.cg.shared.global [%0], [%1], 16;"
                             :: "r"(sa), "l"(g));
            }
        }
        #pragma unroll
        for (int arr = 0; arr < 2; ++arr) {
            const char* s = arr ? srcB_lo : srcB_hi;
            const uint32_t so = sbase + 2 * A_SUB + arr * B_SUB;
            #pragma unroll
            for (int v = 0; v < 4; ++v) {
                int idx = v * 256 + tid;          // 0..1023
                int row = idx >> 3;
                int kb  = (idx & 7) << 4;
                const char* g = s + (size_t)row * (KDIM * 2) + chunk * 128 + kb;
                uint32_t sa = so + row * 128 + (kb ^ ((row & 7) << 4));
                asm volatile("cp.async.cg.shared.global [%0], [%1], 16;"
                             :: "r"(sa), "l"(g));
            }
        }
        asm volatile("cp.async.commit_group;" ::: "memory");
    };

    int aRow = wm * 64 + (L & 15);                  // + mt*16
    int aKb  = (L >> 4) * 16;
    int bRow = wn * 64 + ((L >> 4) << 3) + (L & 7); // + ng*16
    int bKb  = ((L >> 3) & 1) * 16;

    uint32_t aOff[4], aXor[4];
    #pragma unroll
    for (int mt = 0; mt < 4; ++mt) {
        int r = aRow + mt * 16;
        aOff[mt] = r * 128;
        aXor[mt] = (r & 7) << 4;
    }
    uint32_t bOff[4], bXor[4];
    #pragma unroll
    for (int ng = 0; ng < 4; ++ng) {
        int r = bRow + ng * 16;
        bOff[ng] = r * 128;
        bXor[ng] = (r & 7) << 4;
    }

    float acc[4][8][4];
    #pragma unroll
    for (int i = 0; i < 4; ++i)
        #pragma unroll
        for (int j = 0; j < 8; ++j)
            #pragma unroll
            for (int k = 0; k < 4; ++k) acc[i][j][k] = 0.0f;

    load_stage(0, 0);
    load_stage(1, 1);

    for (int i = 0; i < NCHUNK; ++i) {
        const int buf = i & 1;
        if (i + 1 < NCHUNK)
            asm volatile("cp.async.wait_group 1;" ::: "memory");
        else
            asm volatile("cp.async.wait_group 0;" ::: "memory");
        __syncthreads();

        const uint32_t sb  = base + buf * STAGE_BYTES;
        const uint32_t sAh = sb;
        const uint32_t sAl = sb + A_SUB;
        const uint32_t sBh = sb + 2 * A_SUB;
        const uint32_t sBl = sb + 2 * A_SUB + B_SUB;

        #pragma unroll
        for (int ks = 0; ks < 4; ++ks) {
            const uint32_t kA = ks * 32 + aKb;
            const uint32_t kB = ks * 32 + bKb;
            uint32_t ah[4][4], al[4][4];
            #pragma unroll
            for (int mt = 0; mt < 4; ++mt) {
                uint32_t o = aOff[mt] + (kA ^ aXor[mt]);
                ldsm4(ah[mt], sAh + o);
                ldsm4(al[mt], sAl + o);
            }
            #pragma unroll
            for (int ng = 0; ng < 4; ++ng) {
                uint32_t bh[4], bl[4];
                uint32_t o = bOff[ng] + (kB ^ bXor[ng]);
                ldsm4(bh, sBh + o);
                ldsm4(bl, sBl + o);
                #pragma unroll
                for (int mt = 0; mt < 4; ++mt) {
                    #pragma unroll
                    for (int h = 0; h < 2; ++h) {
                        float* c = acc[mt][ng * 2 + h];
                        const uint32_t* fh = &bh[h * 2];
                        const uint32_t* fl = &bl[h * 2];
                        mma16816(c, ah[mt], fh);   // hi*hi
                        mma16816(c, ah[mt], fl);   // hi*lo
                        mma16816(c, al[mt], fh);   // lo*hi
                    }
                }
            }
        }

        __syncthreads();
        if (i + 2 < NCHUNK) load_stage(i + 2, buf);
    }

    #pragma unroll
    for (int mt = 0; mt < 4; ++mt) {
        #pragma unroll
        for (int nt = 0; nt < 8; ++nt) {
            const float* c = acc[mt][nt];
            int row = m0 + wm * 64 + mt * 16 + (L >> 2);
            int col = wn * 64 + nt * 8 + (L & 3) * 2;
            float2 v0, v1;
            v0.x = fmaxf(c[0], 0.0f); v0.y = fmaxf(c[1], 0.0f);
            v1.x = fmaxf(c[2], 0.0f); v1.y = fmaxf(c[3], 0.0f);
            *(float2*)(out + (size_t)row * OUTC + col)       = v0;
            *(float2*)(out + (size_t)(row + 8) * OUTC + col) = v1;
        }
    }
}

// ---------------------------------------------------------------------------
// Kernel 4: concat features2 into out[:, 128:192]
// ---------------------------------------------------------------------------
__global__ __launch_bounds__(256) void concat_kernel(
    const float* __restrict__ feat2, float* __restrict__ out)
{
    const int i = blockIdx.x * blockDim.x + threadIdx.x;
    if (i >= NQ * (C2 / 4)) return;
    const int q = i >> 4;
    const int j = i & 15;
    float4 v = *(const float4*)(feat2 + (size_t)q * C2 + j * 4);
    *(float4*)(out + (size_t)q * OUTC + FOUT + j * 4) = v;
}

// ---------------------------------------------------------------------------
// Launch
// ---------------------------------------------------------------------------
extern "C" void kernel_launch(void* const* d_in, const int* in_sizes, int n_in,
                              void* d_out, int out_size)
{
    const float* xyz1  = (const float*)d_in[0];
    const float* feat1 = (const float*)d_in[1];
    const float* xyz2  = (const float*)d_in[2];
    const float* feat2 = (const float*)d_in[3];
    const float* kp    = (const float*)d_in[4];
    const float* W     = (const float*)d_in[5];
    float* out = (float*)d_out;

    cudaFuncSetAttribute(gemm_kernel,
                         cudaFuncAttributeMaxDynamicSharedMemorySize, GEMM_SMEM);

    knn_kernel<<<dim3(N2 / 256, BATCH), 256>>>(xyz1, xyz2);
    wf_kernel<<<NQ, 64>>>(xyz1, feat1, xyz2, kp);
    wprep_kernel<<<(KDIM * FOUT + 255) / 256, 256>>>(W);
    gemm_kernel<<<NQ / 256, 256, GEMM_SMEM>>>(out);
    concat_kernel<<<(NQ * (C2 / 4) + 255) / 256, 256>>>(feat2, out);
}

// round 6
// speedup vs baseline: 2.5667x; 1.5108x over previous
#include <cuda_runtime.h>
#include <cuda_bf16.h>
#include <cstdint>

// ---------------------------------------------------------------------------
// Problem constants
// ---------------------------------------------------------------------------
#define BATCH   4
#define N1      2048
#define N2      8192
#define C1      128
#define C2      64
#define KP      15
#define FOUT    128
#define NSAMP   16
#define NQ      (BATCH * N2)          // 32768 queries
#define KDIM    (KP * C1)             // 1920
#define OUTC    (FOUT + C2)           // 192
#define NCHUNK  (KDIM / 64)           // 30 K-chunks of 64 bf16

#define GRID    8                     // 8x8x8 spatial bins
#define NCELL   (GRID * GRID * GRID)  // 512
#define CELLH   0.125f

// Scratch (device globals)
__device__ int            g_idx[NQ * NSAMP];
__device__ float4         g_sxyz[BATCH * N1];        // binned points (x,y,z,idx)
__device__ int            g_cellstart[BATCH * (NCELL + 1)];
__device__ __nv_bfloat16  g_a_hi[(size_t)NQ * KDIM];
__device__ __nv_bfloat16  g_a_lo[(size_t)NQ * KDIM];
__device__ __nv_bfloat16  g_b_hi[(size_t)FOUT * KDIM];
__device__ __nv_bfloat16  g_b_lo[(size_t)FOUT * KDIM];

// ---------------------------------------------------------------------------
// Helpers
// ---------------------------------------------------------------------------
__device__ __forceinline__ uint32_t smem_u32(const void* p) {
    uint32_t a;
    asm("{ .reg .u64 t; cvta.to.shared.u64 t, %1; cvt.u32.u64 %0, t; }"
        : "=r"(a) : "l"(p));
    return a;
}
__device__ __forceinline__ void ldsm4(uint32_t* r, uint32_t addr) {
    asm volatile("ldmatrix.sync.aligned.m8n8.x4.shared.b16 {%0,%1,%2,%3}, [%4];"
                 : "=r"(r[0]), "=r"(r[1]), "=r"(r[2]), "=r"(r[3]) : "r"(addr));
}
__device__ __forceinline__ void mma16816(float* c, const uint32_t* a,
                                         const uint32_t* b) {
    asm volatile(
        "mma.sync.aligned.m16n8k16.row.col.f32.bf16.bf16.f32 "
        "{%0,%1,%2,%3}, {%4,%5,%6,%7}, {%8,%9}, {%0,%1,%2,%3};"
        : "+f"(c[0]), "+f"(c[1]), "+f"(c[2]), "+f"(c[3])
        : "r"(a[0]), "r"(a[1]), "r"(a[2]), "r"(a[3]), "r"(b[0]), "r"(b[1]));
}
__device__ __forceinline__ int cellof(float x) {
    int c = (int)(x * (float)GRID);
    return min(GRID - 1, max(0, c));
}

// ---------------------------------------------------------------------------
// Kernel 0: spatial binning, one block (512 threads) per batch.
// Histogram -> exclusive scan -> scatter (coords + original idx in float4.w)
// ---------------------------------------------------------------------------
__global__ __launch_bounds__(512) void bin_kernel(const float* __restrict__ xyz1)
{
    __shared__ int cnt[NCELL];
    __shared__ int sscan[NCELL];
    __shared__ int cursor[NCELL];

    const int b = blockIdx.x;
    const int t = threadIdx.x;

    cnt[t] = 0;
    __syncthreads();

    float px[N1 / 512], py[N1 / 512], pz[N1 / 512];
    int   cl[N1 / 512];
    #pragma unroll
    for (int k = 0; k < N1 / 512; ++k) {
        const int i = t + k * 512;
        px[k] = xyz1[((size_t)b * N1 + i) * 3 + 0];
        py[k] = xyz1[((size_t)b * N1 + i) * 3 + 1];
        pz[k] = xyz1[((size_t)b * N1 + i) * 3 + 2];
        cl[k] = (cellof(pz[k]) << 6) | (cellof(py[k]) << 3) | cellof(px[k]);
        atomicAdd(&cnt[cl[k]], 1);
    }
    __syncthreads();

    // Hillis-Steele inclusive scan, then convert to exclusive
    sscan[t] = cnt[t];
    __syncthreads();
    #pragma unroll
    for (int off = 1; off < NCELL; off <<= 1) {
        int add = (t >= off) ? sscan[t - off] : 0;
        __syncthreads();
        sscan[t] += add;
        __syncthreads();
    }
    const int excl = sscan[t] - cnt[t];
    g_cellstart[b * (NCELL + 1) + t] = excl;
    if (t == NCELL - 1) g_cellstart[b * (NCELL + 1) + NCELL] = N1;
    cursor[t] = excl;
    __syncthreads();

    #pragma unroll
    for (int k = 0; k < N1 / 512; ++k) {
        const int i = t + k * 512;
        const int pos = atomicAdd(&cursor[cl[k]], 1);
        g_sxyz[b * N1 + pos] = make_float4(px[k], py[k], pz[k], __int_as_float(i));
    }
}

// ---------------------------------------------------------------------------
// Kernel 1: kNN via expanding Chebyshev shells over the bin grid.
// One thread per query; binned points (32KB) + cell starts in smem.
// Exact: stop when d16 < (R*h)^2 after completing shell R (fallback: all).
// ---------------------------------------------------------------------------
__global__ __launch_bounds__(256) void knn_kernel(const float* __restrict__ xyz2)
{
    __shared__ float4 spt[N1];            // 32KB
    __shared__ int    cst[NCELL + 1];

    const int b = blockIdx.y;
    for (int i = threadIdx.x; i < N1; i += 256)
        spt[i] = g_sxyz[b * N1 + i];
    for (int i = threadIdx.x; i < NCELL + 1; i += 256)
        cst[i] = g_cellstart[b * (NCELL + 1) + i];
    __syncthreads();

    const int q = b * N2 + blockIdx.x * 256 + threadIdx.x;
    const float qx = xyz2[q * 3 + 0];
    const float qy = xyz2[q * 3 + 1];
    const float qz = xyz2[q * 3 + 2];
    const int cx = cellof(qx), cy = cellof(qy), cz = cellof(qz);

    float dk[NSAMP];
    int   ik[NSAMP];
    #pragma unroll
    for (int p = 0; p < NSAMP; ++p) { dk[p] = 3.4e38f; ik[p] = 0; }

    for (int R = 0; R < GRID; ++R) {
        const int zlo = max(cz - R, 0), zhi = min(cz + R, GRID - 1);
        const int ylo = max(cy - R, 0), yhi = min(cy + R, GRID - 1);
        const int xlo = max(cx - R, 0), xhi = min(cx + R, GRID - 1);
        for (int z = zlo; z <= zhi; ++z) {
            const int az = abs(z - cz);
            for (int y = ylo; y <= yhi; ++y) {
                const int ay = abs(y - cy);
                for (int x = xlo; x <= xhi; ++x) {
                    const int ax = abs(x - cx);
                    if (max(max(az, ay), ax) != R) continue;  // shell only
                    const int cell = (z << 6) | (y << 3) | x;
                    const int e = cst[cell + 1];
                    for (int p = cst[cell]; p < e; ++p) {
                        const float4 P = spt[p];
                        const float dx = qx - P.x;
                        const float dy = qy - P.y;
                        const float dz = qz - P.z;
                        const float d2 = fmaf(dx, dx, fmaf(dy, dy, dz * dz));
                        if (d2 < dk[NSAMP - 1]) {
                            dk[NSAMP - 1] = d2;
                            ik[NSAMP - 1] = __float_as_int(P.w);
                            #pragma unroll
                            for (int s = NSAMP - 1; s > 0; --s) {
                                if (dk[s] < dk[s - 1]) {
                                    float td = dk[s]; dk[s] = dk[s-1]; dk[s-1] = td;
                                    int   ti = ik[s]; ik[s] = ik[s-1]; ik[s-1] = ti;
                                }
                            }
                        }
                    }
                }
            }
        }
        const float bnd = (float)R * CELLH;
        if (dk[NSAMP - 1] < bnd * bnd) break;    // unexamined >= R*h away
    }

    int* o = g_idx + q * NSAMP;
    #pragma unroll
    for (int p = 0; p < NSAMP; ++p) o[p] = ik[p];
}

// ---------------------------------------------------------------------------
// Kernel 2: kernel-point weights + weighted aggregation, bf16-split output.
// 64 threads per query; thread t owns channels (2t, 2t+1).
// ---------------------------------------------------------------------------
__global__ __launch_bounds__(64) void wf_kernel(
    const float* __restrict__ xyz1, const float* __restrict__ feat1,
    const float* __restrict__ xyz2, const float* __restrict__ kp)
{
    const int q = blockIdx.x;
    const int b = q >> 13;
    const int t = threadIdx.x;

    __shared__ int   sid[NSAMP];
    __shared__ float skp[KP * 3];
    __shared__ float sw[NSAMP][KP];

    if (t < KP * 3) skp[t] = kp[t];
    if (t < NSAMP)  sid[t] = g_idx[q * NSAMP + t];
    __syncthreads();

    if (t < NSAMP) {
        const int ni = sid[t];
        const float rx = xyz1[((size_t)b * N1 + ni) * 3 + 0] - xyz2[q * 3 + 0];
        const float ry = xyz1[((size_t)b * N1 + ni) * 3 + 1] - xyz2[q * 3 + 1];
        const float rz = xyz1[((size_t)b * N1 + ni) * 3 + 2] - xyz2[q * 3 + 2];
        #pragma unroll
        for (int k = 0; k < KP; ++k) {
            float dx = rx - skp[k * 3 + 0];
            float dy = ry - skp[k * 3 + 1];
            float dz = rz - skp[k * 3 + 2];
            float sq = dx * dx + dy * dy + dz * dz;
            float dist = sqrtf(fmaxf(sq, 1e-12f));
            sw[t][k] = fmaxf(0.0f, 1.0f - dist / 0.2f);
        }
    }
    __syncthreads();

    const float* fb = feat1 + (size_t)b * N1 * C1;
    float2 f[NSAMP];
    #pragma unroll
    for (int s = 0; s < NSAMP; ++s)
        f[s] = *(const float2*)(fb + (size_t)sid[s] * C1 + 2 * t);

    float ax[KP], ay[KP];
    #pragma unroll
    for (int k = 0; k < KP; ++k) { ax[k] = 0.0f; ay[k] = 0.0f; }
    #pragma unroll
    for (int s = 0; s < NSAMP; ++s) {
        const float fx = f[s].x, fy = f[s].y;
        #pragma unroll
        for (int k = 0; k < KP; ++k) {
            float w = sw[s][k];
            ax[k] = fmaf(w, fx, ax[k]);
            ay[k] = fmaf(w, fy, ay[k]);
        }
    }

    const size_t qbase = (size_t)q * KDIM + 2 * t;
    #pragma unroll
    for (int k = 0; k < KP; ++k) {
        float vx = ax[k], vy = ay[k];
        __nv_bfloat16 hx = __float2bfloat16(vx);
        __nv_bfloat16 hy = __float2bfloat16(vy);
        __nv_bfloat162 hi; hi.x = hx; hi.y = hy;
        __nv_bfloat162 lo;
        lo.x = __float2bfloat16(vx - __bfloat162float(hx));
        lo.y = __float2bfloat16(vy - __bfloat162float(hy));
        *(__nv_bfloat162*)(g_a_hi + qbase + k * C1) = hi;
        *(__nv_bfloat162*)(g_a_lo + qbase + k * C1) = lo;
    }
}

// ---------------------------------------------------------------------------
// Kernel 2b: split + transpose W -> B^T (f, kc), bf16 hi/lo
// ---------------------------------------------------------------------------
__global__ __launch_bounds__(256) void wprep_kernel(const float* __restrict__ W)
{
    const int i = blockIdx.x * blockDim.x + threadIdx.x;
    if (i >= KDIM * FOUT) return;
    const int kc = i / FOUT;
    const int f  = i % FOUT;
    float w = W[i];
    __nv_bfloat16 h = __float2bfloat16(w);
    g_b_hi[(size_t)f * KDIM + kc] = h;
    g_b_lo[(size_t)f * KDIM + kc] = __float2bfloat16(w - __bfloat162float(h));
}

// ---------------------------------------------------------------------------
// Kernel 3: mma.sync bf16 GEMM (2-way split, 3 products), relu epilogue.
// M=32768 (128 CTAs of 256 rows), N=128, K=1920 in 30 chunks of 64.
// 8 warps in 4(M)x2(N): warp tile 64x64. Double-buffered cp.async, 192KB smem.
// ---------------------------------------------------------------------------
#define A_SUB       32768               // 256 rows x 128B
#define B_SUB       16384               // 128 rows x 128B
#define STAGE_BYTES (2 * A_SUB + 2 * B_SUB)   // 96KB
#define GEMM_SMEM   (2 * STAGE_BYTES)          // 192KB

__global__ __launch_bounds__(256, 1)
void gemm_kernel(float* __restrict__ out)
{
    extern __shared__ __align__(1024) char dsmem[];

    const int tid = threadIdx.x;
    const int wid = tid >> 5;
    const int L   = tid & 31;
    const int m0  = blockIdx.x * 256;
    const int wm  = wid & 3;              // 0..3 (M, 64 rows each)
    const int wn  = wid >> 2;             // 0..1 (N, 64 cols each)

    const uint32_t base = smem_u32(dsmem);

    const char* srcA_hi = (const char*)g_a_hi + (size_t)m0 * (KDIM * 2);
    const char* srcA_lo = (const char*)g_a_lo + (size_t)m0 * (KDIM * 2);
    const char* srcB_hi = (const char*)g_b_hi;
    const char* srcB_lo = (const char*)g_b_lo;

    auto load_stage = [&](int chunk, int buf) {
        const uint32_t sbase = base + buf * STAGE_BYTES;
        #pragma unroll
        for (int arr = 0; arr < 2; ++arr) {
            const char* s = arr ? srcA_lo : srcA_hi;
            const uint32_t so = sbase + arr * A_SUB;
            #pragma unroll
            for (int v = 0; v < 8; ++v) {
                int idx = v * 256 + tid;          // 0..2047
                int row = idx >> 3;
                int kb  = (idx & 7) << 4;
                const char* g = s + (size_t)row * (KDIM * 2) + chunk * 128 + kb;
                uint32_t sa = so + row * 128 + (kb ^ ((row & 7) << 4));
                asm volatile("cp.async.cg.shared.global [%0], [%1], 16;"
                             :: "r"(sa), "l"(g));
            }
        }
        #pragma unroll
        for (int arr = 0; arr < 2; ++arr) {
            const char* s = arr ? srcB_lo : srcB_hi;
            const uint32_t so = sbase + 2 * A_SUB + arr * B_SUB;
            #pragma unroll
            for (int v = 0; v < 4; ++v) {
                int idx = v * 256 + tid;          // 0..1023
                int row = idx >> 3;
                int kb  = (idx & 7) << 4;
                const char* g = s + (size_t)row * (KDIM * 2) + chunk * 128 + kb;
                uint32_t sa = so + row * 128 + (kb ^ ((row & 7) << 4));
                asm volatile("cp.async.cg.shared.global [%0], [%1], 16;"
                             :: "r"(sa), "l"(g));
            }
        }
        asm volatile("cp.async.commit_group;" ::: "memory");
    };

    int aRow = wm * 64 + (L & 15);                  // + mt*16
    int aKb  = (L >> 4) * 16;
    int bRow = wn * 64 + ((L >> 4) << 3) + (L & 7); // + ng*16
    int bKb  = ((L >> 3) & 1) * 16;

    uint32_t aOff[4], aXor[4];
    #pragma unroll
    for (int mt = 0; mt < 4; ++mt) {
        int r = aRow + mt * 16;
        aOff[mt] = r * 128;
        aXor[mt] = (r & 7) << 4;
    }
    uint32_t bOff[4], bXor[4];
    #pragma unroll
    for (int ng = 0; ng < 4; ++ng) {
        int r = bRow + ng * 16;
        bOff[ng] = r * 128;
        bXor[ng] = (r & 7) << 4;
    }

    float acc[4][8][4];
    #pragma unroll
    for (int i = 0; i < 4; ++i)
        #pragma unroll
        for (int j = 0; j < 8; ++j)
            #pragma unroll
            for (int k = 0; k < 4; ++k) acc[i][j][k] = 0.0f;

    load_stage(0, 0);
    load_stage(1, 1);

    for (int i = 0; i < NCHUNK; ++i) {
        const int buf = i & 1;
        if (i + 1 < NCHUNK)
            asm volatile("cp.async.wait_group 1;" ::: "memory");
        else
            asm volatile("cp.async.wait_group 0;" ::: "memory");
        __syncthreads();

        const uint32_t sb  = base + buf * STAGE_BYTES;
        const uint32_t sAh = sb;
        const uint32_t sAl = sb + A_SUB;
        const uint32_t sBh = sb + 2 * A_SUB;
        const uint32_t sBl = sb + 2 * A_SUB + B_SUB;

        #pragma unroll
        for (int ks = 0; ks < 4; ++ks) {
            const uint32_t kA = ks * 32 + aKb;
            const uint32_t kB = ks * 32 + bKb;
            uint32_t ah[4][4], al[4][4];
            #pragma unroll
            for (int mt = 0; mt < 4; ++mt) {
                uint32_t o = aOff[mt] + (kA ^ aXor[mt]);
                ldsm4(ah[mt], sAh + o);
                ldsm4(al[mt], sAl + o);
            }
            #pragma unroll
            for (int ng = 0; ng < 4; ++ng) {
                uint32_t bh[4], bl[4];
                uint32_t o = bOff[ng] + (kB ^ bXor[ng]);
                ldsm4(bh, sBh + o);
                ldsm4(bl, sBl + o);
                #pragma unroll
                for (int mt = 0; mt < 4; ++mt) {
                    #pragma unroll
                    for (int h = 0; h < 2; ++h) {
                        float* c = acc[mt][ng * 2 + h];
                        const uint32_t* fh = &bh[h * 2];
                        const uint32_t* fl = &bl[h * 2];
                        mma16816(c, ah[mt], fh);   // hi*hi
                        mma16816(c, ah[mt], fl);   // hi*lo
                        mma16816(c, al[mt], fh);   // lo*hi
                    }
                }
            }
        }

        __syncthreads();
        if (i + 2 < NCHUNK) load_stage(i + 2, buf);
    }

    #pragma unroll
    for (int mt = 0; mt < 4; ++mt) {
        #pragma unroll
        for (int nt = 0; nt < 8; ++nt) {
            const float* c = acc[mt][nt];
            int row = m0 + wm * 64 + mt * 16 + (L >> 2);
            int col = wn * 64 + nt * 8 + (L & 3) * 2;
            float2 v0, v1;
            v0.x = fmaxf(c[0], 0.0f); v0.y = fmaxf(c[1], 0.0f);
            v1.x = fmaxf(c[2], 0.0f); v1.y = fmaxf(c[3], 0.0f);
            *(float2*)(out + (size_t)row * OUTC + col)       = v0;
            *(float2*)(out + (size_t)(row + 8) * OUTC + col) = v1;
        }
    }
}

// ---------------------------------------------------------------------------
// Kernel 4: concat features2 into out[:, 128:192]
// ---------------------------------------------------------------------------
__global__ __launch_bounds__(256) void concat_kernel(
    const float* __restrict__ feat2, float* __restrict__ out)
{
    const int i = blockIdx.x * blockDim.x + threadIdx.x;
    if (i >= NQ * (C2 / 4)) return;
    const int q = i >> 4;
    const int j = i & 15;
    float4 v = *(const float4*)(feat2 + (size_t)q * C2 + j * 4);
    *(float4*)(out + (size_t)q * OUTC + FOUT + j * 4) = v;
}

// ---------------------------------------------------------------------------
// Launch
// ---------------------------------------------------------------------------
extern "C" void kernel_launch(void* const* d_in, const int* in_sizes, int n_in,
                              void* d_out, int out_size)
{
    const float* xyz1  = (const float*)d_in[0];
    const float* feat1 = (const float*)d_in[1];
    const float* xyz2  = (const float*)d_in[2];
    const float* feat2 = (const float*)d_in[3];
    const float* kp    = (const float*)d_in[4];
    const float* W     = (const float*)d_in[5];
    float* out = (float*)d_out;

    cudaFuncSetAttribute(gemm_kernel,
                         cudaFuncAttributeMaxDynamicSharedMemorySize, GEMM_SMEM);

    bin_kernel<<<BATCH, 512>>>(xyz1);
    knn_kernel<<<dim3(N2 / 256, BATCH), 256>>>(xyz2);
    wf_kernel<<<NQ, 64>>>(xyz1, feat1, xyz2, kp);
    wprep_kernel<<<(KDIM * FOUT + 255) / 256, 256>>>(W);
    gemm_kernel<<<NQ / 256, 256, GEMM_SMEM>>>(out);
    concat_kernel<<<(NQ * (C2 / 4) + 255) / 256, 256>>>(feat2, out);
}

// round 7
// speedup vs baseline: 2.6349x; 1.0266x over previous
#include <cuda_runtime.h>
#include <cuda_bf16.h>
#include <cstdint>

// ---------------------------------------------------------------------------
// Problem constants
// ---------------------------------------------------------------------------
#define BATCH   4
#define N1      2048
#define N2      8192
#define C1      128
#define C2      64
#define KP      15
#define FOUT    128
#define NSAMP   16
#define NQ      (BATCH * N2)          // 32768 queries
#define KDIM    (KP * C1)             // 1920
#define OUTC    (FOUT + C2)           // 192
#define NCHUNK  (KDIM / 64)           // 30 K-chunks of 64 bf16

#define GRID    8                     // 8x8x8 spatial bins
#define NCELL   (GRID * GRID * GRID)  // 512
#define CELLH   0.125f

// Scratch (device globals)
__device__ int            g_idx[NQ * NSAMP];
__device__ float4         g_sxyz[BATCH * N1];        // binned points (x,y,z,idx)
__device__ int            g_cellstart[BATCH * (NCELL + 1)];
__device__ __nv_bfloat16  g_a_hi[(size_t)NQ * KDIM];
__device__ __nv_bfloat16  g_a_lo[(size_t)NQ * KDIM];
__device__ __nv_bfloat16  g_b_hi[(size_t)FOUT * KDIM];
__device__ __nv_bfloat16  g_b_lo[(size_t)FOUT * KDIM];

// ---------------------------------------------------------------------------
// Helpers
// ---------------------------------------------------------------------------
__device__ __forceinline__ uint32_t smem_u32(const void* p) {
    uint32_t a;
    asm("{ .reg .u64 t; cvta.to.shared.u64 t, %1; cvt.u32.u64 %0, t; }"
        : "=r"(a) : "l"(p));
    return a;
}
__device__ __forceinline__ void ldsm4(uint32_t* r, uint32_t addr) {
    asm volatile("ldmatrix.sync.aligned.m8n8.x4.shared.b16 {%0,%1,%2,%3}, [%4];"
                 : "=r"(r[0]), "=r"(r[1]), "=r"(r[2]), "=r"(r[3]) : "r"(addr));
}
__device__ __forceinline__ void mma16816(float* c, const uint32_t* a,
                                         const uint32_t* b) {
    asm volatile(
        "mma.sync.aligned.m16n8k16.row.col.f32.bf16.bf16.f32 "
        "{%0,%1,%2,%3}, {%4,%5,%6,%7}, {%8,%9}, {%0,%1,%2,%3};"
        : "+f"(c[0]), "+f"(c[1]), "+f"(c[2]), "+f"(c[3])
        : "r"(a[0]), "r"(a[1]), "r"(a[2]), "r"(a[3]), "r"(b[0]), "r"(b[1]));
}
__device__ __forceinline__ int cellof(float x) {
    int c = (int)(x * (float)GRID);
    return min(GRID - 1, max(0, c));
}

// packed f32x2 (sm_100+ PTX, base family feature)
#define FFMA2(acc, a, b) \
    asm("fma.rn.f32x2 %0, %1, %2, %0;" : "+l"(acc) : "l"(a), "l"(b))
#define PACKF2(out, lo, hi) \
    asm("mov.b64 %0, {%1, %2};" : "=l"(out) : "f"(lo), "f"(hi))
#define UNPACKF2(lo, hi, in) \
    asm("mov.b64 {%0, %1}, %2;" : "=f"(lo), "=f"(hi) : "l"(in))
#define CVTBF2(res, hi, lo) \
    asm("cvt.rn.bf16x2.f32 %0, %1, %2;" : "=r"(res) : "f"(hi), "f"(lo))

// ---------------------------------------------------------------------------
// Kernel 0: prep = spatial binning (blocks 0..3) + W split/transpose (4..483)
// ---------------------------------------------------------------------------
__global__ __launch_bounds__(512) void prep_kernel(
    const float* __restrict__ xyz1, const float* __restrict__ W)
{
    const int t = threadIdx.x;

    if (blockIdx.x >= BATCH) {
        // wprep: 480 blocks x 512 threads = 245760 = KDIM*FOUT elements
        const int i = (blockIdx.x - BATCH) * 512 + t;
        const int kc = i / FOUT;
        const int f  = i % FOUT;
        float w = W[i];
        __nv_bfloat16 h = __float2bfloat16(w);
        g_b_hi[(size_t)f * KDIM + kc] = h;
        g_b_lo[(size_t)f * KDIM + kc] = __float2bfloat16(w - __bfloat162float(h));
        return;
    }

    __shared__ int cnt[NCELL];
    __shared__ int sscan[NCELL];
    __shared__ int cursor[NCELL];

    const int b = blockIdx.x;
    cnt[t] = 0;
    __syncthreads();

    float px[N1 / 512], py[N1 / 512], pz[N1 / 512];
    int   cl[N1 / 512];
    #pragma unroll
    for (int k = 0; k < N1 / 512; ++k) {
        const int i = t + k * 512;
        px[k] = xyz1[((size_t)b * N1 + i) * 3 + 0];
        py[k] = xyz1[((size_t)b * N1 + i) * 3 + 1];
        pz[k] = xyz1[((size_t)b * N1 + i) * 3 + 2];
        cl[k] = (cellof(pz[k]) << 6) | (cellof(py[k]) << 3) | cellof(px[k]);
        atomicAdd(&cnt[cl[k]], 1);
    }
    __syncthreads();

    sscan[t] = cnt[t];
    __syncthreads();
    #pragma unroll
    for (int off = 1; off < NCELL; off <<= 1) {
        int add = (t >= off) ? sscan[t - off] : 0;
        __syncthreads();
        sscan[t] += add;
        __syncthreads();
    }
    const int excl = sscan[t] - cnt[t];
    g_cellstart[b * (NCELL + 1) + t] = excl;
    if (t == NCELL - 1) g_cellstart[b * (NCELL + 1) + NCELL] = N1;
    cursor[t] = excl;
    __syncthreads();

    #pragma unroll
    for (int k = 0; k < N1 / 512; ++k) {
        const int i = t + k * 512;
        const int pos = atomicAdd(&cursor[cl[k]], 1);
        g_sxyz[b * N1 + pos] = make_float4(px[k], py[k], pz[k], __int_as_float(i));
    }
}

// ---------------------------------------------------------------------------
// Kernel 1: kNN via expanding Chebyshev shells over the bin grid.
// ---------------------------------------------------------------------------
__global__ __launch_bounds__(256) void knn_kernel(const float* __restrict__ xyz2)
{
    __shared__ float4 spt[N1];            // 32KB
    __shared__ int    cst[NCELL + 1];

    const int b = blockIdx.y;
    for (int i = threadIdx.x; i < N1; i += 256)
        spt[i] = g_sxyz[b * N1 + i];
    for (int i = threadIdx.x; i < NCELL + 1; i += 256)
        cst[i] = g_cellstart[b * (NCELL + 1) + i];
    __syncthreads();

    const int q = b * N2 + blockIdx.x * 256 + threadIdx.x;
    const float qx = xyz2[q * 3 + 0];
    const float qy = xyz2[q * 3 + 1];
    const float qz = xyz2[q * 3 + 2];
    const int cx = cellof(qx), cy = cellof(qy), cz = cellof(qz);

    float dk[NSAMP];
    int   ik[NSAMP];
    #pragma unroll
    for (int p = 0; p < NSAMP; ++p) { dk[p] = 3.4e38f; ik[p] = 0; }

    for (int R = 0; R < GRID; ++R) {
        const int zlo = max(cz - R, 0), zhi = min(cz + R, GRID - 1);
        const int ylo = max(cy - R, 0), yhi = min(cy + R, GRID - 1);
        const int xlo = max(cx - R, 0), xhi = min(cx + R, GRID - 1);
        for (int z = zlo; z <= zhi; ++z) {
            const int az = abs(z - cz);
            for (int y = ylo; y <= yhi; ++y) {
                const int ay = abs(y - cy);
                for (int x = xlo; x <= xhi; ++x) {
                    const int ax = abs(x - cx);
                    if (max(max(az, ay), ax) != R) continue;  // shell only
                    const int cell = (z << 6) | (y << 3) | x;
                    const int e = cst[cell + 1];
                    for (int p = cst[cell]; p < e; ++p) {
                        const float4 P = spt[p];
                        const float dx = qx - P.x;
                        const float dy = qy - P.y;
                        const float dz = qz - P.z;
                        const float d2 = fmaf(dx, dx, fmaf(dy, dy, dz * dz));
                        if (d2 < dk[NSAMP - 1]) {
                            dk[NSAMP - 1] = d2;
                            ik[NSAMP - 1] = __float_as_int(P.w);
                            #pragma unroll
                            for (int s = NSAMP - 1; s > 0; --s) {
                                if (dk[s] < dk[s - 1]) {
                                    float td = dk[s]; dk[s] = dk[s-1]; dk[s-1] = td;
                                    int   ti = ik[s]; ik[s] = ik[s-1]; ik[s-1] = ti;
                                }
                            }
                        }
                    }
                }
            }
        }
        const float bnd = (float)R * CELLH;
        if (dk[NSAMP - 1] < bnd * bnd) break;
    }

    int* o = g_idx + q * NSAMP;
    #pragma unroll
    for (int p = 0; p < NSAMP; ++p) o[p] = ik[p];
}

// ---------------------------------------------------------------------------
// Kernel 2: weighted aggregation with packed f32x2 FMA.
// 128 threads = 4 warps; one warp per query; each lane owns 4 channels.
// Weights duplicated as float2 in smem -> ld.shared.b64 broadcast multiplier.
// ---------------------------------------------------------------------------
__global__ __launch_bounds__(128) void wf_kernel(
    const float* __restrict__ xyz1, const float* __restrict__ feat1,
    const float* __restrict__ xyz2, const float* __restrict__ kp)
{
    const int wid = threadIdx.x >> 5;
    const int L   = threadIdx.x & 31;
    const int q   = blockIdx.x * 4 + wid;
    const int b   = q >> 13;

    __shared__ float  skp[KP * 3];
    __shared__ float2 sw2[4][NSAMP][KP];   // duplicated weight pairs

    if (threadIdx.x < KP * 3) skp[threadIdx.x] = kp[threadIdx.x];
    __syncthreads();

    int sid = 0;
    if (L < NSAMP) {
        sid = g_idx[q * NSAMP + L];
        const float rx = xyz1[((size_t)b * N1 + sid) * 3 + 0] - xyz2[q * 3 + 0];
        const float ry = xyz1[((size_t)b * N1 + sid) * 3 + 1] - xyz2[q * 3 + 1];
        const float rz = xyz1[((size_t)b * N1 + sid) * 3 + 2] - xyz2[q * 3 + 2];
        #pragma unroll
        for (int k = 0; k < KP; ++k) {
            float dx = rx - skp[k * 3 + 0];
            float dy = ry - skp[k * 3 + 1];
            float dz = rz - skp[k * 3 + 2];
            float sq = dx * dx + dy * dy + dz * dz;
            float dist = sqrtf(fmaxf(sq, 1e-12f));
            float wt = fmaxf(0.0f, 1.0f - dist / 0.2f);
            sw2[wid][L][k] = make_float2(wt, wt);
        }
    }
    __syncwarp();

    // gather: lane L owns channels [4L, 4L+4)
    const float* fb = feat1 + (size_t)b * N1 * C1;
    unsigned long long fxy[NSAMP], fzw[NSAMP];
    #pragma unroll
    for (int s = 0; s < NSAMP; ++s) {
        const int is = __shfl_sync(0xffffffffu, sid, s);
        const float4 v = *(const float4*)(fb + (size_t)is * C1 + 4 * L);
        PACKF2(fxy[s], v.x, v.y);
        PACKF2(fzw[s], v.z, v.w);
    }

    unsigned long long a0[KP], a1[KP];
    #pragma unroll
    for (int k = 0; k < KP; ++k) { a0[k] = 0ull; a1[k] = 0ull; }

    #pragma unroll
    for (int s = 0; s < NSAMP; ++s) {
        #pragma unroll
        for (int k = 0; k < KP; ++k) {
            const unsigned long long wp =
                *(const unsigned long long*)&sw2[wid][s][k];
            FFMA2(a0[k], wp, fxy[s]);
            FFMA2(a1[k], wp, fzw[s]);
        }
    }

    // split + store: 4 channels -> 2x bf16x2 per array
    const size_t qbase = (size_t)q * KDIM + 4 * L;
    #pragma unroll
    for (int k = 0; k < KP; ++k) {
        float vx, vy, vz, vw;
        UNPACKF2(vx, vy, a0[k]);
        UNPACKF2(vz, vw, a1[k]);
        uint32_t h0, h1;
        CVTBF2(h0, vy, vx);
        CVTBF2(h1, vw, vz);
        // bf16 -> f32 bits: low half <<16, high half masked
        float hx = __uint_as_float(h0 << 16);
        float hy = __uint_as_float(h0 & 0xFFFF0000u);
        float hz = __uint_as_float(h1 << 16);
        float hw = __uint_as_float(h1 & 0xFFFF0000u);
        uint32_t l0, l1;
        CVTBF2(l0, vy - hy, vx - hx);
        CVTBF2(l1, vw - hw, vz - hz);
        uint2 hi; hi.x = h0; hi.y = h1;
        uint2 lo; lo.x = l0; lo.y = l1;
        *(uint2*)(g_a_hi + qbase + k * C1) = hi;
        *(uint2*)(g_a_lo + qbase + k * C1) = lo;
    }
}

// ---------------------------------------------------------------------------
// Kernel 3: mma.sync bf16 GEMM (2-way split, 3 products), relu epilogue,
// plus fused concat of features2 into out[:, 128:192].
// ---------------------------------------------------------------------------
#define A_SUB       32768               // 256 rows x 128B
#define B_SUB       16384               // 128 rows x 128B
#define STAGE_BYTES (2 * A_SUB + 2 * B_SUB)   // 96KB
#define GEMM_SMEM   (2 * STAGE_BYTES)          // 192KB

__global__ __launch_bounds__(256, 1)
void gemm_kernel(const float* __restrict__ feat2, float* __restrict__ out)
{
    extern __shared__ __align__(1024) char dsmem[];

    const int tid = threadIdx.x;
    const int wid = tid >> 5;
    const int L   = tid & 31;
    const int m0  = blockIdx.x * 256;
    const int wm  = wid & 3;              // 0..3 (M, 64 rows each)
    const int wn  = wid >> 2;             // 0..1 (N, 64 cols each)

    const uint32_t base = smem_u32(dsmem);

    const char* srcA_hi = (const char*)g_a_hi + (size_t)m0 * (KDIM * 2);
    const char* srcA_lo = (const char*)g_a_lo + (size_t)m0 * (KDIM * 2);
    const char* srcB_hi = (const char*)g_b_hi;
    const char* srcB_lo = (const char*)g_b_lo;

    auto load_stage = [&](int chunk, int buf) {
        const uint32_t sbase = base + buf * STAGE_BYTES;
        #pragma unroll
        for (int arr = 0; arr < 2; ++arr) {
            const char* s = arr ? srcA_lo : srcA_hi;
            const uint32_t so = sbase + arr * A_SUB;
            #pragma unroll
            for (int v = 0; v < 8; ++v) {
                int idx = v * 256 + tid;          // 0..2047
                int row = idx >> 3;
                int kb  = (idx & 7) << 4;
                const char* g = s + (size_t)row * (KDIM * 2) + chunk * 128 + kb;
                uint32_t sa = so + row * 128 + (kb ^ ((row & 7) << 4));
                asm volatile("cp.async.cg.shared.global [%0], [%1], 16;"
                             :: "r"(sa), "l"(g));
            }
        }
        #pragma unroll
        for (int arr = 0; arr < 2; ++arr) {
            const char* s = arr ? srcB_lo : srcB_hi;
            const uint32_t so = sbase + 2 * A_SUB + arr * B_SUB;
            #pragma unroll
            for (int v = 0; v < 4; ++v) {
                int idx = v * 256 + tid;          // 0..1023
                int row = idx >> 3;
                int kb  = (idx & 7) << 4;
                const char* g = s + (size_t)row * (KDIM * 2) + chunk * 128 + kb;
                uint32_t sa = so + row * 128 + (kb ^ ((row & 7) << 4));
                asm volatile("cp.async.cg.shared.global [%0], [%1], 16;"
                             :: "r"(sa), "l"(g));
            }
        }
        asm volatile("cp.async.commit_group;" ::: "memory");
    };

    int aRow = wm * 64 + (L & 15);                  // + mt*16
    int aKb  = (L >> 4) * 16;
    int bRow = wn * 64 + ((L >> 4) << 3) + (L & 7); // + ng*16
    int bKb  = ((L >> 3) & 1) * 16;

    uint32_t aOff[4], aXor[4];
    #pragma unroll
    for (int mt = 0; mt < 4; ++mt) {
        int r = aRow + mt * 16;
        aOff[mt] = r * 128;
        aXor[mt] = (r & 7) << 4;
    }
    uint32_t bOff[4], bXor[4];
    #pragma unroll
    for (int ng = 0; ng < 4; ++ng) {
        int r = bRow + ng * 16;
        bOff[ng] = r * 128;
        bXor[ng] = (r & 7) << 4;
    }

    float acc[4][8][4];
    #pragma unroll
    for (int i = 0; i < 4; ++i)
        #pragma unroll
        for (int j = 0; j < 8; ++j)
            #pragma unroll
            for (int k = 0; k < 4; ++k) acc[i][j][k] = 0.0f;

    load_stage(0, 0);
    load_stage(1, 1);

    // fused concat: copy feat2 rows [m0, m0+256) into out[:,128:192)
    {
        const float* f2 = feat2 + (size_t)m0 * C2;
        float* o2 = out + (size_t)m0 * OUTC + FOUT;
        #pragma unroll
        for (int i = 0; i < 16; ++i) {
            int v = i * 256 + tid;            // 0..4095
            int row = v >> 4;
            int j   = v & 15;
            float4 t = *(const float4*)(f2 + (size_t)row * C2 + j * 4);
            *(float4*)(o2 + (size_t)row * OUTC + j * 4) = t;
        }
    }

    for (int i = 0; i < NCHUNK; ++i) {
        const int buf = i & 1;
        if (i + 1 < NCHUNK)
            asm volatile("cp.async.wait_group 1;" ::: "memory");
        else
            asm volatile("cp.async.wait_group 0;" ::: "memory");
        __syncthreads();

        const uint32_t sb  = base + buf * STAGE_BYTES;
        const uint32_t sAh = sb;
        const uint32_t sAl = sb + A_SUB;
        const uint32_t sBh = sb + 2 * A_SUB;
        const uint32_t sBl = sb + 2 * A_SUB + B_SUB;

        #pragma unroll
        for (int ks = 0; ks < 4; ++ks) {
            const uint32_t kA = ks * 32 + aKb;
            const uint32_t kB = ks * 32 + bKb;
            uint32_t ah[4][4], al[4][4];
            #pragma unroll
            for (int mt = 0; mt < 4; ++mt) {
                uint32_t o = aOff[mt] + (kA ^ aXor[mt]);
                ldsm4(ah[mt], sAh + o);
                ldsm4(al[mt], sAl + o);
            }
            #pragma unroll
            for (int ng = 0; ng < 4; ++ng) {
                uint32_t bh[4], bl[4];
                uint32_t o = bOff[ng] + (kB ^ bXor[ng]);
                ldsm4(bh, sBh + o);
                ldsm4(bl, sBl + o);
                #pragma unroll
                for (int mt = 0; mt < 4; ++mt) {
                    #pragma unroll
                    for (int h = 0; h < 2; ++h) {
                        float* c = acc[mt][ng * 2 + h];
                        const uint32_t* fh = &bh[h * 2];
                        const uint32_t* fl = &bl[h * 2];
                        mma16816(c, ah[mt], fh);   // hi*hi
                        mma16816(c, ah[mt], fl);   // hi*lo
                        mma16816(c, al[mt], fh);   // lo*hi
                    }
                }
            }
        }

        __syncthreads();
        if (i + 2 < NCHUNK) load_stage(i + 2, buf);
    }

    #pragma unroll
    for (int mt = 0; mt < 4; ++mt) {
        #pragma unroll
        for (int nt = 0; nt < 8; ++nt) {
            const float* c = acc[mt][nt];
            int row = m0 + wm * 64 + mt * 16 + (L >> 2);
            int col = wn * 64 + nt * 8 + (L & 3) * 2;
            float2 v0, v1;
            v0.x = fmaxf(c[0], 0.0f); v0.y = fmaxf(c[1], 0.0f);
            v1.x = fmaxf(c[2], 0.0f); v1.y = fmaxf(c[3], 0.0f);
            *(float2*)(out + (size_t)row * OUTC + col)       = v0;
            *(float2*)(out + (size_t)(row + 8) * OUTC + col) = v1;
        }
    }
}

// ---------------------------------------------------------------------------
// Launch
// ---------------------------------------------------------------------------
extern "C" void kernel_launch(void* const* d_in, const int* in_sizes, int n_in,
                              void* d_out, int out_size)
{
    const float* xyz1  = (const float*)d_in[0];
    const float* feat1 = (const float*)d_in[1];
    const float* xyz2  = (const float*)d_in[2];
    const float* feat2 = (const float*)d_in[3];
    const float* kp    = (const float*)d_in[4];
    const float* W     = (const float*)d_in[5];
    float* out = (float*)d_out;

    cudaFuncSetAttribute(gemm_kernel,
                         cudaFuncAttributeMaxDynamicSharedMemorySize, GEMM_SMEM);

    prep_kernel<<<BATCH + (KDIM * FOUT) / 512, 512>>>(xyz1, W);
    knn_kernel<<<dim3(N2 / 256, BATCH), 256>>>(xyz2);
    wf_kernel<<<NQ / 4, 128>>>(xyz1, feat1, xyz2, kp);
    gemm_kernel<<<NQ / 256, 256, GEMM_SMEM>>>(feat2, out);
}